// round 3
// baseline (speedup 1.0000x reference)
#include <cuda_runtime.h>
#include <stdint.h>

// Row layout: segments (u,v) = (128,1),(64,3),(32,5),(16,7), total 592.
// out[off + a*u + b] = in[off + b*v + a]
// output column c: a=(c-off)>>log2(u), b=(c-off)&(u-1); src = off + b*v + a

#define ROW_DIM 592
#define RPB 4                           // rows per buffer
#define TILE_FLOATS (ROW_DIM * RPB)     // 2368
#define TILE_VEC4   (TILE_FLOATS / 4)   // 592
#define NT 256

__device__ __forceinline__ int perm_src(int c) {
    if (c < 128) return c;
    if (c < 320) { int l = c - 128; return 128 + (l & 63) * 3 + (l >> 6); }
    if (c < 480) { int l = c - 320; return 320 + (l & 31) * 5 + (l >> 5); }
    { int l = c - 480; return 480 + (l & 15) * 7 + (l >> 4); }
}

__device__ __forceinline__ void cp_async16(void* smem_dst, const void* gmem_src) {
    unsigned d = (unsigned)__cvta_generic_to_shared(smem_dst);
    asm volatile("cp.async.cg.shared.global [%0], [%1], 16;" :: "r"(d), "l"(gmem_src) : "memory");
}

__device__ __forceinline__ void cp_commit() {
    asm volatile("cp.async.commit_group;" ::: "memory");
}

__device__ __forceinline__ void cp_wait1() {
    asm volatile("cp.async.wait_group 1;" ::: "memory");
}

__global__ __launch_bounds__(NT, 8)
void transpose_irreps_cpasync(const float* __restrict__ in, float* __restrict__ out, int n_tiles) {
    __shared__ __align__(16) float buf[2][TILE_FLOATS];
    __shared__ short stab[ROW_DIM];

    const int tid = threadIdx.x;

    for (int c = tid; c < ROW_DIM; c += NT) stab[c] = (short)perm_src(c);
    __syncthreads();

    const int stride = gridDim.x;
    const int t0 = blockIdx.x;

    // Prologue: async-load first tile into buf 0
    if (t0 < n_tiles) {
        const float* src = in + (long long)t0 * TILE_FLOATS;
        #pragma unroll
        for (int i = tid; i < TILE_VEC4; i += NT)
            cp_async16(&buf[0][4 * i], src + 4 * i);
    }
    cp_commit();

    int bi = 0;
    for (int t = t0; t < n_tiles; t += stride) {
        // Issue prefetch of next tile into the other buffer.
        // (Safe: end-of-previous-iteration __syncthreads guarantees all
        //  reads of that buffer completed.)
        int tn = t + stride;
        if (tn < n_tiles) {
            const float* src = in + (long long)tn * TILE_FLOATS;
            int nb = bi ^ 1;
            #pragma unroll
            for (int i = tid; i < TILE_VEC4; i += NT)
                cp_async16(&buf[nb][4 * i], src + 4 * i);
        }
        cp_commit();            // always commit -> group counts stay aligned

        cp_wait1();             // current tile's group (older) is complete
        __syncthreads();

        // Permuted stores: lane-consecutive c -> coalesced STG.32,
        // conflict-free LDS gather (odd strides 1/3/5/7).
        float* __restrict__ ob = out + (long long)t * TILE_FLOATS;
        const float* __restrict__ bb = &buf[bi][0];
        #pragma unroll
        for (int i = tid; i < TILE_FLOATS; i += NT) {
            int r = i / ROW_DIM;              // const-divide -> mul/shift
            int c = i - r * ROW_DIM;
            ob[i] = bb[r * ROW_DIM + (int)stab[c]];
        }

        __syncthreads();        // reads of buf[bi] done before it is refilled
        bi ^= 1;
    }
}

extern "C" void kernel_launch(void* const* d_in, const int* in_sizes, int n_in,
                              void* d_out, int out_size) {
    const float* x = (const float*)d_in[0];
    float* out = (float*)d_out;
    int n_rows = in_sizes[0] / ROW_DIM;     // 200000
    int n_tiles = n_rows / RPB;             // 50000 (exact)
    int grid = 148 * 8;                     // persistent, 8 CTAs/SM target
    if (grid > n_tiles) grid = n_tiles;
    transpose_irreps_cpasync<<<grid, NT>>>(x, out, n_tiles);
}

// round 4
// speedup vs baseline: 1.0942x; 1.0942x over previous
#include <cuda_runtime.h>
#include <stdint.h>

// Row layout: segments (u,v) = (128,1),(64,3),(32,5),(16,7), total 592 fp32.
// out[off + a*u + b] = in[off + b*v + a]
// For output column c: a = (c-off)>>log2(u), b = (c-off)&(u-1); src = off + b*v + a.
// Segment boundaries (128, 320, 480) are multiples of 32 -> no warp divergence.

#define ROW_DIM 592
#define NT 256
#define IPT 4   // float4 groups per thread

__device__ __forceinline__ int perm_src(int c) {
    if (c < 128) return c;
    if (c < 320) { int l = c - 128; return 128 + (l & 63) * 3 + (l >> 6); }
    if (c < 480) { int l = c - 320; return 320 + (l & 31) * 5 + (l >> 5); }
    { int l = c - 480; return 480 + (l & 15) * 7 + (l >> 4); }
}

__global__ __launch_bounds__(NT)
void transpose_irreps_direct(const float* __restrict__ in,
                             float* __restrict__ out,
                             int n_groups /* total float4 groups */) {
    const int base = blockIdx.x * (NT * IPT) + threadIdx.x;

    #pragma unroll
    for (int k = 0; k < IPT; k++) {
        int g = base + k * NT;           // float4 group index
        if (g < n_groups) {
            int e = 4 * g;               // element index (fits in int: <2^31)
            int row = e / ROW_DIM;       // const divide -> mulhi/shift
            int c = e - row * ROW_DIM;   // 0..588, multiple of 4
            const float* __restrict__ rb = in + row * ROW_DIM;
            float4 v;
            v.x = __ldg(rb + perm_src(c));
            v.y = __ldg(rb + perm_src(c + 1));
            v.z = __ldg(rb + perm_src(c + 2));
            v.w = __ldg(rb + perm_src(c + 3));
            *reinterpret_cast<float4*>(out + e) = v;
        }
    }
}

extern "C" void kernel_launch(void* const* d_in, const int* in_sizes, int n_in,
                              void* d_out, int out_size) {
    const float* x = (const float*)d_in[0];
    float* out = (float*)d_out;
    int n_elems = in_sizes[0];               // 118,400,000
    int n_groups = n_elems / 4;              // 29,600,000 (row dim 592 is 4-aligned)
    int per_block = NT * IPT;
    int grid = (n_groups + per_block - 1) / per_block;
    transpose_irreps_direct<<<grid, NT>>>(x, out, n_groups);
}

// round 5
// speedup vs baseline: 1.1481x; 1.0493x over previous
#include <cuda_runtime.h>
#include <stdint.h>

// Row layout: segments (u,v) = (128,1),(64,3),(32,5),(16,7), total 592 fp32.
// out[off + a*u + b] = in[off + b*v + a]
// For output column c: a = (c-off)>>log2(u), b = (c-off)&(u-1); src = off + b*v + a

#define ROW_DIM 592
#define RPB 4                                   // rows per block
#define NT 128                                  // threads per block
#define FLOATS_PER_BLOCK (ROW_DIM * RPB)        // 2368
#define VEC4_PER_BLOCK (FLOATS_PER_BLOCK / 4)   // 592

__device__ __forceinline__ int perm_src(int c) {
    if (c < 128) return c;
    if (c < 320) { int l = c - 128; return 128 + (l & 63) * 3 + (l >> 6); }
    if (c < 480) { int l = c - 320; return 320 + (l & 31) * 5 + (l >> 5); }
    { int l = c - 480; return 480 + (l & 15) * 7 + (l >> 4); }
}

__global__ __launch_bounds__(NT, 16)
void transpose_irreps_fine(const float* __restrict__ in, float* __restrict__ out) {
    __shared__ __align__(16) float smem[FLOATS_PER_BLOCK];

    const int tid = threadIdx.x;
    const long long block_elem_base = (long long)blockIdx.x * FLOATS_PER_BLOCK;

    // Phase 1: coalesced vectorized streaming loads of 4 rows into smem
    const float4* __restrict__ in4 = reinterpret_cast<const float4*>(in + block_elem_base);
    float4* __restrict__ sm4 = reinterpret_cast<float4*>(smem);
    #pragma unroll
    for (int i = tid; i < VEC4_PER_BLOCK; i += NT) {
        sm4[i] = __ldcs(in4 + i);
    }
    __syncthreads();

    // Phase 2: coalesced streaming stores; conflict-free smem gather
    // (lane stride within a warp = v in {1,3,5,7}, all odd -> no bank conflicts)
    float* __restrict__ out_base = out + block_elem_base;
    #pragma unroll
    for (int cb = 0; cb < ROW_DIM; cb += NT) {
        int c = cb + tid;
        if (c < ROW_DIM) {
            int s = perm_src(c);
            #pragma unroll
            for (int r = 0; r < RPB; r++) {
                __stcs(out_base + r * ROW_DIM + c, smem[r * ROW_DIM + s]);
            }
        }
    }
}

extern "C" void kernel_launch(void* const* d_in, const int* in_sizes, int n_in,
                              void* d_out, int out_size) {
    const float* x = (const float*)d_in[0];
    float* out = (float*)d_out;
    int n_rows = in_sizes[0] / ROW_DIM;     // 200000
    int grid = n_rows / RPB;                // 50000 (exact: 200000 % 4 == 0)
    transpose_irreps_fine<<<grid, NT>>>(x, out);
}